// round 6
// baseline (speedup 1.0000x reference)
#include <cuda_runtime.h>
#include <cstdint>
#include <cstddef>

#define TT_   512
#define BB_   256
#define HID   128
#define GATE  512
#define KSM0  100          // k-rows of W_hh in smem  ([k][512] = [k][t][2] packed pairs)
#define KRG0  28           // k-rows of W_hh in registers (ull pairs)

// Scratch (static device globals — allocation is forbidden)
__device__ float g_h1 [(size_t)TT_ * BB_ * 2 * HID];   // layer-0 output [t][b][256]
__device__ float g_g1f[(size_t)TT_ * BB_ * GATE];      // layer-1 fwd precomputed input gates
__device__ float g_h2f[BB_ * HID];                     // layer-1 fwd final h

// ---------------- packed f32x2 helpers ----------------
__device__ __forceinline__ unsigned long long pack2(float lo, float hi) {
    unsigned long long r;
    asm("mov.b64 %0, {%1, %2};" : "=l"(r) : "f"(lo), "f"(hi));
    return r;
}
__device__ __forceinline__ unsigned long long dup2(float v) {
    unsigned long long r;
    asm("mov.b64 %0, {%1, %1};" : "=l"(r) : "f"(v));
    return r;
}
__device__ __forceinline__ void unpack2(unsigned long long v, float& lo, float& hi) {
    asm("mov.b64 {%0, %1}, %2;" : "=f"(lo), "=f"(hi) : "l"(v));
}
__device__ __forceinline__ void ffma2(unsigned long long& d, unsigned long long a, unsigned long long b) {
    asm("fma.rn.f32x2 %0, %1, %2, %0;" : "+l"(d) : "l"(a), "l"(b));
}

// ---------------- activations (accurate ~1e-6) ----------------
__device__ __forceinline__ float sigm_f(float x) {
    return __fdividef(1.0f, 1.0f + __expf(-x));
}
__device__ __forceinline__ float tanh_f(float x) {
    float a = fabsf(x);
    float e = __expf(-2.0f * a);
    float r = __fdividef(1.0f - e, 1.0f + e);
    return copysignf(r, x);
}

// =====================================================================================
// Kernel 1: layer-0 bidirectional recurrence — GATE-PAIR scheme.
// grid (64,2), 256 threads. Thread t owns gate columns j0=2t, j1=2t+1 for 4 batch rows.
// Inner loop per k: LDS.64 (w_j0,w_j1) + 2x LDS.128 broadcast of duplicated h + 4 FFMA2.
// Gate exchange through smem for the cell update (2 syncs/step).
// =====================================================================================
extern "C" __global__ void __launch_bounds__(256, 1)
lstm_l0(const float* __restrict__ x,
        const float* __restrict__ Wih_f, const float* __restrict__ Whh_f, const float* __restrict__ bv_f,
        const float* __restrict__ Wih_b, const float* __restrict__ Whh_b, const float* __restrict__ bv_b)
{
    extern __shared__ float sm0[];
    float* Wsm = sm0;                      // [KSM0][512]   Wsm[k*512 + col] = Whh[col*128+k]
    float* hsm = sm0 + KSM0 * 512;         // [2][128][8]   (h,h) duplicated, 4 batch rows
    float* gsm = hsm + 2048;               // [4][512]      gate pre-activations
    float* xsm = gsm + 2048;               // [2][12]

    const int tid = threadIdx.x;
    const int dir = blockIdx.y;
    const int b0  = blockIdx.x * 4;
    const int j0  = 2 * tid;               // gate columns owned
    const float* __restrict__ Wih = dir ? Wih_b : Wih_f;
    const float* __restrict__ Whh = dir ? Whh_b : Whh_f;
    const float* __restrict__ bv  = dir ? bv_b  : bv_f;

    // W_hh low-k -> smem: Wsm[k][col] = Whh[col][k]
    for (int idx = tid; idx < KSM0 * 512; idx += 256) {
        int k = idx >> 9, col = idx & 511;
        Wsm[idx] = Whh[col * HID + k];
    }
    // W_hh high-k -> register ull pairs (w_j0, w_j1)
    unsigned long long wreg[KRG0];
#pragma unroll
    for (int r = 0; r < KRG0; r++)
        wreg[r] = pack2(Whh[j0 * HID + KSM0 + r], Whh[(j0 + 1) * HID + KSM0 + r]);

    // input weights + bias for the two owned gate columns
    float wA0 = Wih[j0 * 3], wA1 = Wih[j0 * 3 + 1], wA2 = Wih[j0 * 3 + 2];
    float wB0 = Wih[(j0 + 1) * 3], wB1 = Wih[(j0 + 1) * 3 + 1], wB2 = Wih[(j0 + 1) * 3 + 2];
    float bA = bv[j0], bB = bv[j0 + 1];

    // zero both duplicated-h buffers (2048 floats)
#pragma unroll
    for (int i = 0; i < 8; i++) hsm[tid + 256 * i] = 0.0f;
    if (tid < 12) {
        int r = tid / 3, i = tid % 3;
        int t0 = dir ? (TT_ - 1) : 0;
        xsm[tid] = x[((size_t)(b0 + r) * TT_ + t0) * 3 + i];
    }
    const int u  = tid & 127;
    const int bs = (tid >> 7) * 2;         // this thread's 2 cells: (u,bs),(u,bs+1)
    float c0 = 0.0f, c1 = 0.0f;
    const float* wp = Wsm + j0;
    __syncthreads();

    for (int s = 0; s < TT_; s++) {
        const int tcur = dir ? (TT_ - 1 - s) : s;
        const int pb = s & 1;

        // acc init: bias + x-projection, packed (gate j0, gate j1) per batch row
        const float* xp = xsm + pb * 12;
        unsigned long long acc[4];
#pragma unroll
        for (int b = 0; b < 4; b++) {
            float xx0 = xp[b * 3], xx1 = xp[b * 3 + 1], xx2 = xp[b * 3 + 2];
            float aA = fmaf(wA2, xx2, fmaf(wA1, xx1, fmaf(wA0, xx0, bA)));
            float aB = fmaf(wB2, xx2, fmaf(wB1, xx1, fmaf(wB0, xx0, bB)));
            acc[b] = pack2(aA, aB);
        }

        const float* hb = hsm + pb * 1024;
#pragma unroll 10
        for (int k = 0; k < KSM0; k++) {
            unsigned long long w2 = *reinterpret_cast<const unsigned long long*>(wp + k * 512);
            ulonglong2 H01 = *reinterpret_cast<const ulonglong2*>(hb + k * 8);
            ulonglong2 H23 = *reinterpret_cast<const ulonglong2*>(hb + k * 8 + 4);
            ffma2(acc[0], w2, H01.x);
            ffma2(acc[1], w2, H01.y);
            ffma2(acc[2], w2, H23.x);
            ffma2(acc[3], w2, H23.y);
        }
#pragma unroll
        for (int r = 0; r < KRG0; r++) {
            ulonglong2 H01 = *reinterpret_cast<const ulonglong2*>(hb + (KSM0 + r) * 8);
            ulonglong2 H23 = *reinterpret_cast<const ulonglong2*>(hb + (KSM0 + r) * 8 + 4);
            ffma2(acc[0], wreg[r], H01.x);
            ffma2(acc[1], wreg[r], H01.y);
            ffma2(acc[2], wreg[r], H23.x);
            ffma2(acc[3], wreg[r], H23.y);
        }
        // publish gate pre-activations: gsm[b][j0..j1]
#pragma unroll
        for (int b = 0; b < 4; b++)
            *reinterpret_cast<unsigned long long*>(gsm + b * 512 + j0) = acc[b];
        __syncthreads();

        // cell update: 2 cells per thread
        {
            const float* g0 = gsm + bs * 512;
            float gi = g0[u], gf = g0[u + 128], gg = g0[u + 256], go = g0[u + 384];
            c0 = sigm_f(gf) * c0 + sigm_f(gi) * tanh_f(gg);
            float h0v = sigm_f(go) * tanh_f(c0);
            const float* g1 = gsm + (bs + 1) * 512;
            gi = g1[u]; gf = g1[u + 128]; gg = g1[u + 256]; go = g1[u + 384];
            c1 = sigm_f(gf) * c1 + sigm_f(gi) * tanh_f(gg);
            float h1v = sigm_f(go) * tanh_f(c1);

            // duplicated h -> other buffer: (h0,h0,h1,h1) one STS.128
            *reinterpret_cast<float4*>(hsm + (pb ^ 1) * 1024 + u * 8 + bs * 2) =
                make_float4(h0v, h0v, h1v, h1v);
            size_t gbase = ((size_t)tcur * BB_ + b0 + bs) * (2 * HID) + dir * HID + u;
            g_h1[gbase] = h0v;
            g_h1[gbase + 2 * HID] = h1v;
        }
        if (s + 1 < TT_ && tid < 12) {     // prefetch next x into other buffer
            int r = tid / 3, i = tid % 3;
            int tn = dir ? (TT_ - 2 - s) : (s + 1);
            xsm[(pb ^ 1) * 12 + tid] = x[((size_t)(b0 + r) * TT_ + tn) * 3 + i];
        }
        __syncthreads();
    }
}

// =====================================================================================
// Kernel 2: layer-1 forward input projection GEMM (unchanged from measured R1 baseline)
//   g_g1f[r][j] = h1[r][:] @ W_ih_l1f[j][:]^T + b_l1f[j]
// =====================================================================================
#define APITCH 68
#define WPITCH 129
extern "C" __global__ void __launch_bounds__(512, 1)
gemm_l1in(const float* __restrict__ W, const float* __restrict__ bias)
{
    extern __shared__ float smg[];
    float* Asm = smg;                    // [256][APITCH]
    float* Wsm = smg + 256 * APITCH;     // [256][WPITCH]

    const int tid  = threadIdx.x;
    const int jblk = blockIdx.x & 3;
    const int tg   = blockIdx.x >> 2;

    for (int idx = tid; idx < 128 * 256; idx += 512) {
        int k = idx & 255, jj = idx >> 8;
        Wsm[k * WPITCH + jj] = W[((jblk << 7) + jj) * 256 + k];
    }

    const int j  = tid & 127;
    const int rg = tid >> 7;
    const float bj = bias[(jblk << 7) + j];
    const unsigned long long bpack = pack2(bj, bj);

    for (int tile = tg; tile < 2048; tile += 37) {
        const size_t r0 = (size_t)tile * 64;
        __syncthreads();
        for (int idx = tid; idx < 64 * 256; idx += 512) {
            int k = idx & 255, row = idx >> 8;
            Asm[k * APITCH + row] = g_h1[(r0 + row) * 256 + k];
        }
        __syncthreads();

        unsigned long long acc[8];
#pragma unroll
        for (int p = 0; p < 8; p++) acc[p] = bpack;

#pragma unroll 4
        for (int k = 0; k < 256; k++) {
            unsigned long long w2 = dup2(Wsm[k * WPITCH + j]);
            const ulonglong2* ap =
                reinterpret_cast<const ulonglong2*>(Asm + k * APITCH + rg * 16);
#pragma unroll
            for (int q = 0; q < 4; q++) {
                ulonglong2 av = ap[q];
                ffma2(acc[2 * q],     w2, av.x);
                ffma2(acc[2 * q + 1], w2, av.y);
            }
        }
#pragma unroll
        for (int p = 0; p < 8; p++) {
            float v0, v1; unpack2(acc[p], v0, v1);
            size_t r = r0 + rg * 16 + 2 * p;
            g_g1f[r * GATE + (jblk << 7) + j]       = v0;
            g_g1f[(r + 1) * GATE + (jblk << 7) + j] = v1;
        }
    }
}

// =====================================================================================
// Kernel 3: layer-1 forward recurrence — GATE-PAIR scheme. grid 128, 256 threads,
// thread owns gate columns (2t, 2t+1) for 2 batch rows; gates streamed from g_g1f
// as natural LDG.64 pairs (bias already folded).
// =====================================================================================
extern "C" __global__ void __launch_bounds__(256, 1)
lstm_l1(const float* __restrict__ Whh)
{
    extern __shared__ float sm1[];
    float* Wsm = sm1;                     // [KSM0][512]
    float* hsm = sm1 + KSM0 * 512;        // [2][128][4]  (h0,h0,h1,h1)
    float* gsm = hsm + 1024;              // [2][512]

    const int tid = threadIdx.x;
    const int b0  = blockIdx.x * 2;
    const int j0  = 2 * tid;

    for (int idx = tid; idx < KSM0 * 512; idx += 256) {
        int k = idx >> 9, col = idx & 511;
        Wsm[idx] = Whh[col * HID + k];
    }
    unsigned long long wreg[KRG0];
#pragma unroll
    for (int r = 0; r < KRG0; r++)
        wreg[r] = pack2(Whh[j0 * HID + KSM0 + r], Whh[(j0 + 1) * HID + KSM0 + r]);

#pragma unroll
    for (int i = 0; i < 4; i++) hsm[tid + 256 * i] = 0.0f;

    // first step's input gates (LDG.64 natural pairs)
    unsigned long long p0 = *reinterpret_cast<const unsigned long long*>(
        g_g1f + (size_t)(b0 + 0) * GATE + j0);
    unsigned long long p1 = *reinterpret_cast<const unsigned long long*>(
        g_g1f + (size_t)(b0 + 1) * GATE + j0);

    const int u = tid & 127, bsel = tid >> 7;
    float c = 0.0f;
    const float* wp = Wsm + j0;
    __syncthreads();

    for (int s = 0; s < TT_; s++) {
        const int pb = s & 1;
        unsigned long long acc0 = p0, acc1 = p1;

        if (s + 1 < TT_) {                 // prefetch next step (hidden under inner loop)
            size_t rn = (size_t)(s + 1) * BB_ + b0;
            p0 = *reinterpret_cast<const unsigned long long*>(g_g1f + rn * GATE + j0);
            p1 = *reinterpret_cast<const unsigned long long*>(g_g1f + (rn + 1) * GATE + j0);
        }

        const float* hb = hsm + pb * 512;
#pragma unroll 10
        for (int k = 0; k < KSM0; k++) {
            unsigned long long w2 = *reinterpret_cast<const unsigned long long*>(wp + k * 512);
            ulonglong2 H = *reinterpret_cast<const ulonglong2*>(hb + k * 4);
            ffma2(acc0, w2, H.x);
            ffma2(acc1, w2, H.y);
        }
#pragma unroll
        for (int r = 0; r < KRG0; r++) {
            ulonglong2 H = *reinterpret_cast<const ulonglong2*>(hb + (KSM0 + r) * 4);
            ffma2(acc0, wreg[r], H.x);
            ffma2(acc1, wreg[r], H.y);
        }
        *reinterpret_cast<unsigned long long*>(gsm + 0 * 512 + j0) = acc0;
        *reinterpret_cast<unsigned long long*>(gsm + 1 * 512 + j0) = acc1;
        __syncthreads();

        {   // one cell per thread: (u, bsel)
            const float* g = gsm + bsel * 512;
            float gi = g[u], gf = g[u + 128], gg = g[u + 256], go = g[u + 384];
            c = sigm_f(gf) * c + sigm_f(gi) * tanh_f(gg);
            float h = sigm_f(go) * tanh_f(c);
            *reinterpret_cast<float2*>(hsm + (pb ^ 1) * 512 + u * 4 + bsel * 2) =
                make_float2(h, h);
            if (s == TT_ - 1) g_h2f[(b0 + bsel) * HID + u] = h;
        }
        __syncthreads();
    }
}

// =====================================================================================
// Kernel 4: layer-1 backward single step + FC. grid 64 CTAs x 4 batch rows.
// =====================================================================================
extern "C" __global__ void __launch_bounds__(512, 1)
final_k(const float* __restrict__ Wihb, const float* __restrict__ bvb,
        const float* __restrict__ Wfc,  const float* __restrict__ bfc,
        float* __restrict__ out)
{
    __shared__ float h1s[4 * 256];
    __shared__ float hfs[4 * 128];
    __shared__ float gates[4 * 512];
    __shared__ float hbs[4 * 128];

    const int tid = threadIdx.x;
    const int b0  = blockIdx.x * 4;

    for (int idx = tid; idx < 4 * 256; idx += 512) {
        int r = idx >> 8, k = idx & 255;
        h1s[idx] = g_h1[((size_t)(TT_ - 1) * BB_ + b0 + r) * 256 + k];
    }
    if (tid < 4 * 128)
        hfs[tid] = g_h2f[b0 * HID + tid];
    __syncthreads();

    float acc[4];
    const float bj = bvb[tid];
#pragma unroll
    for (int r = 0; r < 4; r++) acc[r] = bj;
    const float* wr = Wihb + (size_t)tid * 256;
#pragma unroll 4
    for (int k = 0; k < 256; k++) {
        float w = wr[k];
#pragma unroll
        for (int r = 0; r < 4; r++) acc[r] = fmaf(h1s[r * 256 + k], w, acc[r]);
    }
#pragma unroll
    for (int r = 0; r < 4; r++) gates[r * 512 + tid] = acc[r];
    __syncthreads();

    {   // one cell per thread (512 cells = 4 rows x 128 u)
        int r = tid >> 7, u = tid & 127;
        float gi = gates[r * 512 + u];
        float gg = gates[r * 512 + u + 256];
        float go = gates[r * 512 + u + 384];
        float c  = sigm_f(gi) * tanh_f(gg);          // f-gate x c0 = 0
        hbs[r * 128 + u] = sigm_f(go) * tanh_f(c);
    }
    __syncthreads();

    if (tid < 24) {
        int r = tid / 6, o = tid % 6;
        const float* wf = Wfc + o * 256;
        float s0 = bfc[o], s1 = 0.0f;
#pragma unroll 4
        for (int jj = 0; jj < 128; jj++) {
            s0 = fmaf(hfs[r * 128 + jj], wf[jj],       s0);
            s1 = fmaf(hbs[r * 128 + jj], wf[128 + jj], s1);
        }
        out[(b0 + r) * 6 + o] = s0 + s1;
    }
}

// =====================================================================================
extern "C" void kernel_launch(void* const* d_in, const int* in_sizes, int n_in,
                              void* d_out, int out_size)
{
    (void)in_sizes; (void)n_in; (void)out_size;
    const float* x     = (const float*)d_in[0];
    const float* Wih0f = (const float*)d_in[1];
    const float* Whh0f = (const float*)d_in[2];
    const float* b0f   = (const float*)d_in[3];
    const float* Wih0b = (const float*)d_in[4];
    const float* Whh0b = (const float*)d_in[5];
    const float* b0b   = (const float*)d_in[6];
    const float* Wih1f = (const float*)d_in[7];
    const float* Whh1f = (const float*)d_in[8];
    const float* b1f   = (const float*)d_in[9];
    const float* Wih1b = (const float*)d_in[10];
    const float* Whh1b = (const float*)d_in[11];
    const float* b1b   = (const float*)d_in[12];
    const float* Wfc   = (const float*)d_in[13];
    const float* bfc   = (const float*)d_in[14];
    float* out = (float*)d_out;

    const int SM_L0 = (KSM0 * 512 + 2048 + 2048 + 24) * 4;   // 221,280 B
    const int SM_G  = (256 * APITCH + 256 * WPITCH) * 4;     // 201,728 B
    const int SM_L1 = (KSM0 * 512 + 1024 + 1024) * 4;        // 212,992 B

    cudaFuncSetAttribute(lstm_l0,   cudaFuncAttributeMaxDynamicSharedMemorySize, SM_L0);
    cudaFuncSetAttribute(gemm_l1in, cudaFuncAttributeMaxDynamicSharedMemorySize, SM_G);
    cudaFuncSetAttribute(lstm_l1,   cudaFuncAttributeMaxDynamicSharedMemorySize, SM_L1);

    lstm_l0<<<dim3(64, 2), 256, SM_L0>>>(x, Wih0f, Whh0f, b0f, Wih0b, Whh0b, b0b);
    gemm_l1in<<<148, 512, SM_G>>>(Wih1f, b1f);
    lstm_l1<<<128, 256, SM_L1>>>(Whh1f);
    final_k<<<64, 512>>>(Wih1b, b1b, Wfc, bfc, out);
}

// round 7
// speedup vs baseline: 1.0703x; 1.0703x over previous
#include <cuda_runtime.h>
#include <cstdint>
#include <cstddef>

#define TT_   512
#define BB_   256
#define HID   128
#define GATE  512
#define KSMH  36           // k-rows per group in smem
#define KRGH  28           // k-rows per group in registers (36+28 = 64 per group)

// Scratch (static device globals — allocation is forbidden)
__device__ float g_h1 [(size_t)TT_ * BB_ * 2 * HID];   // layer-0 output [t][b][256]
__device__ float g_g1f[(size_t)TT_ * BB_ * GATE];      // layer-1 fwd precomputed input gates
__device__ float g_h2f[BB_ * HID];                     // layer-1 fwd final h

// ---------------- packed f32x2 helpers ----------------
__device__ __forceinline__ unsigned long long pack2(float lo, float hi) {
    unsigned long long r;
    asm("mov.b64 %0, {%1, %2};" : "=l"(r) : "f"(lo), "f"(hi));
    return r;
}
__device__ __forceinline__ unsigned long long dup2(float v) {
    unsigned long long r;
    asm("mov.b64 %0, {%1, %1};" : "=l"(r) : "f"(v));
    return r;
}
__device__ __forceinline__ void unpack2(unsigned long long v, float& lo, float& hi) {
    asm("mov.b64 {%0, %1}, %2;" : "=f"(lo), "=f"(hi) : "l"(v));
}
__device__ __forceinline__ void ffma2(unsigned long long& d, unsigned long long a, unsigned long long b) {
    asm("fma.rn.f32x2 %0, %1, %2, %0;" : "+l"(d) : "l"(a), "l"(b));
}

// ---------------- activations (accurate ~1e-6) ----------------
__device__ __forceinline__ float sigm_f(float x) {
    return __fdividef(1.0f, 1.0f + __expf(-x));
}
__device__ __forceinline__ float tanh_f(float x) {
    float a = fabsf(x);
    float e = __expf(-2.0f * a);
    float r = __fdividef(1.0f - e, 1.0f + e);
    return copysignf(r, x);
}

// =====================================================================================
// Kernel 1: layer-0 bidirectional recurrence — GATE-PAIR + SPLIT-K.
// grid (64,2), 512 threads = 2 k-groups x 256. Group g owns k in [64g, 64g+64):
// 36 k-rows from smem, 28 from registers. Thread (g, t) computes partial gate
// pre-activations for columns j0=2t, j1=2t+1, 4 batch rows. Partials summed in the
// cell phase (1 cell per thread). 4 warps/SMSP for latency hiding.
// =====================================================================================
extern "C" __global__ void __launch_bounds__(512, 1)
lstm_l0(const float* __restrict__ x,
        const float* __restrict__ Wih_f, const float* __restrict__ Whh_f, const float* __restrict__ bv_f,
        const float* __restrict__ Wih_b, const float* __restrict__ Whh_b, const float* __restrict__ bv_b)
{
    extern __shared__ float sm0[];
    float* Wsm = sm0;                      // [2][KSMH][512]
    float* hsm = sm0 + 2 * KSMH * 512;     // [2][128][8]   (h,h) duplicated, 4 rows
    float* gsm = hsm + 2048;               // [2][4][512]   partial gates per group
    float* xsm = gsm + 4096;               // [2][12]

    const int tid = threadIdx.x;
    const int g   = tid >> 8;              // k-group
    const int t   = tid & 255;
    const int j0  = 2 * t;                 // owned gate columns
    const int dir = blockIdx.y;
    const int b0  = blockIdx.x * 4;
    const float* __restrict__ Wih = dir ? Wih_b : Wih_f;
    const float* __restrict__ Whh = dir ? Whh_b : Whh_f;
    const float* __restrict__ bv  = dir ? bv_b  : bv_f;

    // W_hh -> smem: Wsm[g][kk][col] = Whh[col][g*64+kk]
    for (int idx = tid; idx < 2 * KSMH * 512; idx += 512) {
        int gg  = idx / (KSMH * 512);
        int rem = idx - gg * (KSMH * 512);
        int kk  = rem >> 9, col = rem & 511;
        Wsm[idx] = Whh[col * HID + gg * 64 + kk];
    }
    // W_hh high-k of this group's range -> register ull pairs
    unsigned long long wreg[KRGH];
#pragma unroll
    for (int r = 0; r < KRGH; r++) {
        int k = g * 64 + KSMH + r;
        wreg[r] = pack2(Whh[j0 * HID + k], Whh[(j0 + 1) * HID + k]);
    }

    // input weights + bias (used by group 0 only)
    float wA0 = Wih[j0 * 3], wA1 = Wih[j0 * 3 + 1], wA2 = Wih[j0 * 3 + 2];
    float wB0 = Wih[(j0 + 1) * 3], wB1 = Wih[(j0 + 1) * 3 + 1], wB2 = Wih[(j0 + 1) * 3 + 2];
    float bA = bv[j0], bB = bv[j0 + 1];

    // zero both duplicated-h buffers
#pragma unroll
    for (int i = 0; i < 4; i++) hsm[tid + 512 * i] = 0.0f;
    if (tid < 12) {
        int r = tid / 3, i = tid % 3;
        int t0 = dir ? (TT_ - 1) : 0;
        xsm[tid] = x[((size_t)(b0 + r) * TT_ + t0) * 3 + i];
    }
    const int u  = tid & 127;              // cell assignment: 512 cells = 4 rows x 128
    const int bb = tid >> 7;
    float c = 0.0f;
    const float* wp = Wsm + g * (KSMH * 512) + j0;
    __syncthreads();

    for (int s = 0; s < TT_; s++) {
        const int tcur = dir ? (TT_ - 1 - s) : s;
        const int pb = s & 1;

        unsigned long long acc[4];
        if (g == 0) {                      // bias + x-projection added exactly once
            const float* xp = xsm + pb * 12;
#pragma unroll
            for (int b = 0; b < 4; b++) {
                float xx0 = xp[b * 3], xx1 = xp[b * 3 + 1], xx2 = xp[b * 3 + 2];
                float aA = fmaf(wA2, xx2, fmaf(wA1, xx1, fmaf(wA0, xx0, bA)));
                float aB = fmaf(wB2, xx2, fmaf(wB1, xx1, fmaf(wB0, xx0, bB)));
                acc[b] = pack2(aA, aB);
            }
        } else {
#pragma unroll
            for (int b = 0; b < 4; b++) acc[b] = 0ULL;
        }

        const float* hb = hsm + pb * 1024 + g * (64 * 8);
#pragma unroll 9
        for (int kk = 0; kk < KSMH; kk++) {
            unsigned long long w2 = *reinterpret_cast<const unsigned long long*>(wp + kk * 512);
            ulonglong2 H01 = *reinterpret_cast<const ulonglong2*>(hb + kk * 8);
            ulonglong2 H23 = *reinterpret_cast<const ulonglong2*>(hb + kk * 8 + 4);
            ffma2(acc[0], w2, H01.x);
            ffma2(acc[1], w2, H01.y);
            ffma2(acc[2], w2, H23.x);
            ffma2(acc[3], w2, H23.y);
        }
#pragma unroll
        for (int r = 0; r < KRGH; r++) {
            ulonglong2 H01 = *reinterpret_cast<const ulonglong2*>(hb + (KSMH + r) * 8);
            ulonglong2 H23 = *reinterpret_cast<const ulonglong2*>(hb + (KSMH + r) * 8 + 4);
            ffma2(acc[0], wreg[r], H01.x);
            ffma2(acc[1], wreg[r], H01.y);
            ffma2(acc[2], wreg[r], H23.x);
            ffma2(acc[3], wreg[r], H23.y);
        }
        // publish partial gates: gsm[g][b][j0..j1]
#pragma unroll
        for (int b = 0; b < 4; b++)
            *reinterpret_cast<unsigned long long*>(gsm + g * 2048 + b * 512 + j0) = acc[b];
        __syncthreads();

        // cell update: one cell (u, bb) per thread; sum the two k-group partials
        {
            const float* g0 = gsm + bb * 512;
            const float* g1 = gsm + 2048 + bb * 512;
            float gi = g0[u]       + g1[u];
            float gf = g0[u + 128] + g1[u + 128];
            float gg = g0[u + 256] + g1[u + 256];
            float go = g0[u + 384] + g1[u + 384];
            c = sigm_f(gf) * c + sigm_f(gi) * tanh_f(gg);
            float h = sigm_f(go) * tanh_f(c);

            *reinterpret_cast<float2*>(hsm + (pb ^ 1) * 1024 + u * 8 + bb * 2) =
                make_float2(h, h);
            g_h1[((size_t)tcur * BB_ + b0 + bb) * (2 * HID) + dir * HID + u] = h;
        }
        if (s + 1 < TT_ && tid < 12) {     // prefetch next x into other buffer
            int r = tid / 3, i = tid % 3;
            int tn = dir ? (TT_ - 2 - s) : (s + 1);
            xsm[(pb ^ 1) * 12 + tid] = x[((size_t)(b0 + r) * TT_ + tn) * 3 + i];
        }
        __syncthreads();
    }
}

// =====================================================================================
// Kernel 2: layer-1 forward input projection GEMM (unchanged — measured-pass baseline)
// =====================================================================================
#define APITCH 68
#define WPITCH 129
extern "C" __global__ void __launch_bounds__(512, 1)
gemm_l1in(const float* __restrict__ W, const float* __restrict__ bias)
{
    extern __shared__ float smg[];
    float* Asm = smg;                    // [256][APITCH]
    float* Wsm = smg + 256 * APITCH;     // [256][WPITCH]

    const int tid  = threadIdx.x;
    const int jblk = blockIdx.x & 3;
    const int tg   = blockIdx.x >> 2;

    for (int idx = tid; idx < 128 * 256; idx += 512) {
        int k = idx & 255, jj = idx >> 8;
        Wsm[k * WPITCH + jj] = W[((jblk << 7) + jj) * 256 + k];
    }

    const int j  = tid & 127;
    const int rg = tid >> 7;
    const float bj = bias[(jblk << 7) + j];
    const unsigned long long bpack = pack2(bj, bj);

    for (int tile = tg; tile < 2048; tile += 37) {
        const size_t r0 = (size_t)tile * 64;
        __syncthreads();
        for (int idx = tid; idx < 64 * 256; idx += 512) {
            int k = idx & 255, row = idx >> 8;
            Asm[k * APITCH + row] = g_h1[(r0 + row) * 256 + k];
        }
        __syncthreads();

        unsigned long long acc[8];
#pragma unroll
        for (int p = 0; p < 8; p++) acc[p] = bpack;

#pragma unroll 4
        for (int k = 0; k < 256; k++) {
            unsigned long long w2 = dup2(Wsm[k * WPITCH + j]);
            const ulonglong2* ap =
                reinterpret_cast<const ulonglong2*>(Asm + k * APITCH + rg * 16);
#pragma unroll
            for (int q = 0; q < 4; q++) {
                ulonglong2 av = ap[q];
                ffma2(acc[2 * q],     w2, av.x);
                ffma2(acc[2 * q + 1], w2, av.y);
            }
        }
#pragma unroll
        for (int p = 0; p < 8; p++) {
            float v0, v1; unpack2(acc[p], v0, v1);
            size_t r = r0 + rg * 16 + 2 * p;
            g_g1f[r * GATE + (jblk << 7) + j]       = v0;
            g_g1f[(r + 1) * GATE + (jblk << 7) + j] = v1;
        }
    }
}

// =====================================================================================
// Kernel 3: layer-1 forward recurrence — GATE-PAIR + SPLIT-K. grid 128, 512 threads
// (2 k-groups x 256), 2 batch rows per CTA; precomputed gates streamed by group 0.
// =====================================================================================
extern "C" __global__ void __launch_bounds__(512, 1)
lstm_l1(const float* __restrict__ Whh)
{
    extern __shared__ float sm1[];
    float* Wsm = sm1;                     // [2][KSMH][512]
    float* hsm = sm1 + 2 * KSMH * 512;    // [2][128][4]  (h0,h0,h1,h1)
    float* gsm = hsm + 1024;              // [2][2][512]  partial gates per group

    const int tid = threadIdx.x;
    const int g   = tid >> 8;
    const int t   = tid & 255;
    const int j0  = 2 * t;
    const int b0  = blockIdx.x * 2;

    for (int idx = tid; idx < 2 * KSMH * 512; idx += 512) {
        int gg  = idx / (KSMH * 512);
        int rem = idx - gg * (KSMH * 512);
        int kk  = rem >> 9, col = rem & 511;
        Wsm[idx] = Whh[col * HID + gg * 64 + kk];
    }
    unsigned long long wreg[KRGH];
#pragma unroll
    for (int r = 0; r < KRGH; r++) {
        int k = g * 64 + KSMH + r;
        wreg[r] = pack2(Whh[j0 * HID + k], Whh[(j0 + 1) * HID + k]);
    }

#pragma unroll
    for (int i = 0; i < 2; i++) hsm[tid + 512 * i] = 0.0f;

    // group 0 streams the precomputed input gates (bias folded)
    unsigned long long p0 = 0ULL, p1 = 0ULL;
    if (g == 0) {
        p0 = *reinterpret_cast<const unsigned long long*>(g_g1f + (size_t)(b0 + 0) * GATE + j0);
        p1 = *reinterpret_cast<const unsigned long long*>(g_g1f + (size_t)(b0 + 1) * GATE + j0);
    }

    const int u = tid & 127, bsel = (tid >> 7) & 1;
    const bool docell = tid < 256;
    float c = 0.0f;
    const float* wp = Wsm + g * (KSMH * 512) + j0;
    __syncthreads();

    for (int s = 0; s < TT_; s++) {
        const int pb = s & 1;
        unsigned long long acc0 = p0, acc1 = p1;

        if (g == 0 && s + 1 < TT_) {       // prefetch next step (hidden under inner loop)
            size_t rn = (size_t)(s + 1) * BB_ + b0;
            p0 = *reinterpret_cast<const unsigned long long*>(g_g1f + rn * GATE + j0);
            p1 = *reinterpret_cast<const unsigned long long*>(g_g1f + (rn + 1) * GATE + j0);
        }

        const float* hb = hsm + pb * 512 + g * (64 * 4);
#pragma unroll 9
        for (int kk = 0; kk < KSMH; kk++) {
            unsigned long long w2 = *reinterpret_cast<const unsigned long long*>(wp + kk * 512);
            ulonglong2 H = *reinterpret_cast<const ulonglong2*>(hb + kk * 4);
            ffma2(acc0, w2, H.x);
            ffma2(acc1, w2, H.y);
        }
#pragma unroll
        for (int r = 0; r < KRGH; r++) {
            ulonglong2 H = *reinterpret_cast<const ulonglong2*>(hb + (KSMH + r) * 4);
            ffma2(acc0, wreg[r], H.x);
            ffma2(acc1, wreg[r], H.y);
        }
        *reinterpret_cast<unsigned long long*>(gsm + g * 1024 + 0 * 512 + j0) = acc0;
        *reinterpret_cast<unsigned long long*>(gsm + g * 1024 + 1 * 512 + j0) = acc1;
        __syncthreads();

        if (docell) {                      // one cell (u, bsel) per thread (tid<256)
            const float* ga = gsm + bsel * 512;
            const float* gb2 = gsm + 1024 + bsel * 512;
            float gi = ga[u]       + gb2[u];
            float gf = ga[u + 128] + gb2[u + 128];
            float gg = ga[u + 256] + gb2[u + 256];
            float go = ga[u + 384] + gb2[u + 384];
            c = sigm_f(gf) * c + sigm_f(gi) * tanh_f(gg);
            float h = sigm_f(go) * tanh_f(c);
            *reinterpret_cast<float2*>(hsm + (pb ^ 1) * 512 + u * 4 + bsel * 2) =
                make_float2(h, h);
            if (s == TT_ - 1) g_h2f[(b0 + bsel) * HID + u] = h;
        }
        __syncthreads();
    }
}

// =====================================================================================
// Kernel 4: layer-1 backward single step + FC (unchanged — measured-pass baseline)
// =====================================================================================
extern "C" __global__ void __launch_bounds__(512, 1)
final_k(const float* __restrict__ Wihb, const float* __restrict__ bvb,
        const float* __restrict__ Wfc,  const float* __restrict__ bfc,
        float* __restrict__ out)
{
    __shared__ float h1s[4 * 256];
    __shared__ float hfs[4 * 128];
    __shared__ float gates[4 * 512];
    __shared__ float hbs[4 * 128];

    const int tid = threadIdx.x;
    const int b0  = blockIdx.x * 4;

    for (int idx = tid; idx < 4 * 256; idx += 512) {
        int r = idx >> 8, k = idx & 255;
        h1s[idx] = g_h1[((size_t)(TT_ - 1) * BB_ + b0 + r) * 256 + k];
    }
    if (tid < 4 * 128)
        hfs[tid] = g_h2f[b0 * HID + tid];
    __syncthreads();

    float acc[4];
    const float bj = bvb[tid];
#pragma unroll
    for (int r = 0; r < 4; r++) acc[r] = bj;
    const float* wr = Wihb + (size_t)tid * 256;
#pragma unroll 4
    for (int k = 0; k < 256; k++) {
        float w = wr[k];
#pragma unroll
        for (int r = 0; r < 4; r++) acc[r] = fmaf(h1s[r * 256 + k], w, acc[r]);
    }
#pragma unroll
    for (int r = 0; r < 4; r++) gates[r * 512 + tid] = acc[r];
    __syncthreads();

    {
        int r = tid >> 7, u = tid & 127;
        float gi = gates[r * 512 + u];
        float gg = gates[r * 512 + u + 256];
        float go = gates[r * 512 + u + 384];
        float c  = sigm_f(gi) * tanh_f(gg);          // f-gate x c0 = 0
        hbs[r * 128 + u] = sigm_f(go) * tanh_f(c);
    }
    __syncthreads();

    if (tid < 24) {
        int r = tid / 6, o = tid % 6;
        const float* wf = Wfc + o * 256;
        float s0 = bfc[o], s1 = 0.0f;
#pragma unroll 4
        for (int jj = 0; jj < 128; jj++) {
            s0 = fmaf(hfs[r * 128 + jj], wf[jj],       s0);
            s1 = fmaf(hbs[r * 128 + jj], wf[128 + jj], s1);
        }
        out[(b0 + r) * 6 + o] = s0 + s1;
    }
}

// =====================================================================================
extern "C" void kernel_launch(void* const* d_in, const int* in_sizes, int n_in,
                              void* d_out, int out_size)
{
    (void)in_sizes; (void)n_in; (void)out_size;
    const float* x     = (const float*)d_in[0];
    const float* Wih0f = (const float*)d_in[1];
    const float* Whh0f = (const float*)d_in[2];
    const float* b0f   = (const float*)d_in[3];
    const float* Wih0b = (const float*)d_in[4];
    const float* Whh0b = (const float*)d_in[5];
    const float* b0b   = (const float*)d_in[6];
    const float* Wih1f = (const float*)d_in[7];
    const float* Whh1f = (const float*)d_in[8];
    const float* b1f   = (const float*)d_in[9];
    const float* Wih1b = (const float*)d_in[10];
    const float* Whh1b = (const float*)d_in[11];
    const float* b1b   = (const float*)d_in[12];
    const float* Wfc   = (const float*)d_in[13];
    const float* bfc   = (const float*)d_in[14];
    float* out = (float*)d_out;

    const int SM_L0 = (2 * KSMH * 512 + 2048 + 4096 + 24) * 4;   // 172,128 B
    const int SM_G  = (256 * APITCH + 256 * WPITCH) * 4;         // 201,728 B
    const int SM_L1 = (2 * KSMH * 512 + 1024 + 2048) * 4;        // 159,744 B

    cudaFuncSetAttribute(lstm_l0,   cudaFuncAttributeMaxDynamicSharedMemorySize, SM_L0);
    cudaFuncSetAttribute(gemm_l1in, cudaFuncAttributeMaxDynamicSharedMemorySize, SM_G);
    cudaFuncSetAttribute(lstm_l1,   cudaFuncAttributeMaxDynamicSharedMemorySize, SM_L1);

    lstm_l0<<<dim3(64, 2), 512, SM_L0>>>(x, Wih0f, Whh0f, b0f, Wih0b, Whh0b, b0b);
    gemm_l1in<<<148, 512, SM_G>>>(Wih1f, b1f);
    lstm_l1<<<128, 512, SM_L1>>>(Whh1f);
    final_k<<<64, 512>>>(Wih1b, b1b, Wfc, bfc, out);
}